// round 15
// baseline (speedup 1.0000x reference)
#include <cuda_runtime.h>
#include <cstdint>

// ModulatedConv2D: B=16, Cin=Cout=512, H=W=32, k=3, pad=1.
// out[b,o] = sigma[b,o] * conv2d( x[b,i]*style[b,i], weight*GAIN )[o]
// Implicit GEMM via mma.sync m16n8k8 tf32.
// R15: cp.async double-buffered halo staging; smem convert pass for
// style-mod + tf32 rounding (numerics identical to R14).

#define Bn 16
#define Cn 512
#define On 512
#define GAINF 0.014731391274719738f  // 1/sqrt(512*9)

__device__ float g_wsq[On * Cn];
__device__ float g_sigma[Bn * On];
// A fragments: [tap(9)][otile16(32)][kstep8(64)][lane(32)][4 regs], tf32 bits
__device__ uint32_t g_wA[9 * 32 * 64 * 32 * 4];

// ---------------------------------------------------------------------------
__global__ void wsq_kernel(const float* __restrict__ wt) {
    int idx = blockIdx.x * 256 + threadIdx.x;
    if (idx < On * Cn) {
        const float* p = wt + idx * 9;
        float s = 0.f;
#pragma unroll
        for (int k = 0; k < 9; ++k) { float v = p[k]; s += v * v; }
        g_wsq[idx] = s;
    }
}

// m16n8k8 A layout: a0=(gid,tg) a1=(gid+8,tg) a2=(gid,tg+4) a3=(gid+8,tg+4)
__global__ void wfrag_kernel(const float* __restrict__ wt) {
    int id = blockIdx.x * 256 + threadIdx.x;
    if (id >= 9 * 32 * 64 * 32) return;
    int lane = id & 31;
    int ksg  = (id >> 5) & 63;
    int otg  = (id >> 11) & 31;
    int tap  = id >> 16;
    int gid = lane >> 2, tg = lane & 3;
    int o = otg * 16 + gid;
    int k = ksg * 8 + tg;
    float f0 = wt[((o    ) * Cn + k    ) * 9 + tap] * GAINF;
    float f1 = wt[((o + 8) * Cn + k    ) * 9 + tap] * GAINF;
    float f2 = wt[((o    ) * Cn + k + 4) * 9 + tap] * GAINF;
    float f3 = wt[((o + 8) * Cn + k + 4) * 9 + tap] * GAINF;
    uint32_t u0, u1, u2, u3;
    asm("cvt.rna.tf32.f32 %0, %1;" : "=r"(u0) : "f"(f0));
    asm("cvt.rna.tf32.f32 %0, %1;" : "=r"(u1) : "f"(f1));
    asm("cvt.rna.tf32.f32 %0, %1;" : "=r"(u2) : "f"(f2));
    asm("cvt.rna.tf32.f32 %0, %1;" : "=r"(u3) : "f"(f3));
    ((uint4*)g_wA)[id] = make_uint4(u0, u1, u2, u3);
}

// ---------------------------------------------------------------------------
__global__ void sigma_kernel(const float* __restrict__ style) {
    int o = blockIdx.x, b = blockIdx.y, t = threadIdx.x;
    float s = 0.f;
    for (int i = t; i < Cn; i += 256) {
        float st = style[b * Cn + i];
        s += st * st * g_wsq[o * Cn + i];
    }
    __shared__ float red[8];
#pragma unroll
    for (int off = 16; off; off >>= 1) s += __shfl_xor_sync(0xffffffffu, s, off);
    if ((t & 31) == 0) red[t >> 5] = s;
    __syncthreads();
    if (t < 8) {
        s = red[t];
#pragma unroll
        for (int off = 4; off; off >>= 1) s += __shfl_xor_sync(0xffu, s, off);
        if (t == 0) g_sigma[b * On + o] = rsqrtf(GAINF * GAINF * s + 1e-8f);
    }
}

// ---------------------------------------------------------------------------
// Halo layout: per channel XS=248 floats; row stride 40; x-col c at idx c+4.
// Valid halo cols -1..32 -> idx 3..36. Idx 0..2, 37..39 unused (zero).
// XS mod 32 = 24 -> B-fragment LDS conflict-free (tg*24 + gid covers banks).
// Interior row start idx 4 -> 16B-aligned -> cp.async.cg 16B.
// ---------------------------------------------------------------------------
#define XS 248
#define RS 40

#define MMA_TF32(c, a, bb0, bb1)                                              \
    asm("mma.sync.aligned.m16n8k8.row.col.f32.tf32.tf32.f32 "                 \
        "{%0,%1,%2,%3}, {%4,%5,%6,%7}, {%8,%9}, {%0,%1,%2,%3};"               \
        : "+f"((c)[0]), "+f"((c)[1]), "+f"((c)[2]), "+f"((c)[3])              \
        : "r"((a).x), "r"((a).y), "r"((a).z), "r"((a).w), "r"(bb0), "r"(bb1))

__device__ __forceinline__ uint32_t smem_u32(const void* p) {
    uint32_t a;
    asm("{ .reg .u64 t; cvta.to.shared.u64 t, %1; cvt.u32.u64 %0, t; }" : "=r"(a) : "l"(p));
    return a;
}
__device__ __forceinline__ void cp16(uint32_t dst, const void* src) {
    asm volatile("cp.async.cg.shared.global [%0], [%1], 16;" :: "r"(dst), "l"(src));
}
__device__ __forceinline__ void cp_commit() {
    asm volatile("cp.async.commit_group;" ::: "memory");
}
__device__ __forceinline__ void cp_wait0() {
    asm volatile("cp.async.wait_group 0;" ::: "memory");
}

// issue one chunk's halo cp.asyncs into buffer buf (32 ch x 6 rows x 8 x 16B)
__device__ __forceinline__ void issue_halo(const float* __restrict__ x,
                                           uint32_t sbuf_u32, int bC, int ic0,
                                           int y0, int tid) {
#pragma unroll
    for (int j = 0; j < 6; ++j) {
        int idx = j * 256 + tid;            // 0..1535
        int ch  = idx / 48;
        int rem = idx - ch * 48;
        int r   = rem >> 3;
        int c16 = rem & 7;
        int gy  = y0 + r - 1;
        if ((unsigned)gy < 32u) {
            const float* src = x + ((size_t)(bC + ic0 + ch) * 32 + gy) * 32 + c16 * 4;
            uint32_t dst = sbuf_u32 + (uint32_t)(ch * XS + r * RS + 4 + c16 * 4) * 4u;
            cp16(dst, src);
        }
    }
    cp_commit();
}

__global__ void __launch_bounds__(256, 2)
conv_mma_kernel(const float* __restrict__ x, const float* __restrict__ style,
                float* __restrict__ out) {
    extern __shared__ __align__(16) float sXH[];   // 2 buffers x 32*XS floats

    const int b   = blockIdx.z;
    const int oty = blockIdx.y;          // o-tile: 128 channels
    const int y0  = blockIdx.x * 4;      // 4 output rows
    const int tid = threadIdx.x;
    const int wid = tid >> 5, lane = tid & 31;
    const int warp_m = wid >> 2;         // 0..1 : 64 o-channels
    const int warp_n = wid & 3;          // 0..3 : 32 spatial cols
    const int gid = lane >> 2, tg = lane & 3;
    const int bC = b * Cn;
    const uint32_t sb = smem_u32(sXH);

    // ---- zero both halo buffers (borders + invalid rows stay zero) ----
#pragma unroll
    for (int j = 0; j < 16; ++j) {
        int e = j * 256 + tid;             // float4 index, 2*32*XS/4 = 3968
        if (e < 2 * 32 * XS / 4)
            ((float4*)sXH)[e] = make_float4(0.f, 0.f, 0.f, 0.f);
    }
    __syncthreads();

    // ---- prologue: stream chunk 0 into buffer 0 ----
    issue_halo(x, sb, bC, 0, y0, tid);

    float acc[4][4][4];
#pragma unroll
    for (int mt = 0; mt < 4; ++mt)
#pragma unroll
        for (int nt = 0; nt < 4; ++nt)
#pragma unroll
            for (int c = 0; c < 4; ++c) acc[mt][nt][c] = 0.f;

#pragma unroll 1
    for (int ci = 0; ci < 16; ++ci) {
        const int ic0 = ci * 32;
        float* cur = sXH + (ci & 1) * (32 * XS);

        cp_wait0();
        __syncthreads();   // chunk ci data landed; tap loop of ci-1 finished

        // stream next chunk into the other buffer (overlaps convert + MMAs)
        if (ci < 15)
            issue_halo(x, sb + (uint32_t)((~ci & 1) * (32 * XS)) * 4u,
                       bC, ic0 + 32, y0, tid);

        // ---- convert pass: scale interior by style, round to tf32 ----
#pragma unroll
        for (int j = 0; j < 24; ++j) {
            int idx = j * 256 + tid;        // 32ch x 192 interior elems
            int ch  = idx / 192;
            int rem = idx - ch * 192;
            int r   = rem >> 5;
            int c   = rem & 31;
            float* a = cur + ch * XS + r * RS + 4 + c;
            float v = *a * __ldg(style + bC + ic0 + ch);
            uint32_t u;
            asm("cvt.rna.tf32.f32 %0, %1;" : "=r"(u) : "f"(v));
            *a = __uint_as_float(u);
        }
        __syncthreads();

        // ---- 9 taps x 4 k-steps of MMAs ----
#pragma unroll 1
        for (int tap = 0; tap < 9; ++tap) {
            const int dy = tap / 3, dx = tap - dy * 3;
            const float* pBt = cur + (warp_n + dy) * RS + dx + 3 + tg * XS;
            const uint4* Abase = (const uint4*)g_wA +
                ((tap * 32 + (oty * 8 + warp_m * 4)) * 64 + (ic0 >> 3)) * 32 + lane;
#pragma unroll
            for (int ks = 0; ks < 4; ++ks) {
                uint4 A[4];
#pragma unroll
                for (int mt = 0; mt < 4; ++mt)
                    A[mt] = __ldg(Abase + mt * (64 * 32) + ks * 32);
                const float* pB = pBt + ks * (8 * XS);
                uint32_t b0[4], b1[4];
#pragma unroll
                for (int nt = 0; nt < 4; ++nt) {
                    b0[nt] = __float_as_uint(pB[nt * 8 + gid]);
                    b1[nt] = __float_as_uint(pB[nt * 8 + gid + 4 * XS]);
                }
#pragma unroll
                for (int mt = 0; mt < 4; ++mt)
#pragma unroll
                    for (int nt = 0; nt < 4; ++nt)
                        MMA_TF32(acc[mt][nt], A[mt], b0[nt], b1[nt]);
            }
        }
    }

    // ---- epilogue: demodulate, direct float2 stores ----
    // C layout: c0=(gid, 2tg) c1=(gid, 2tg+1) c2=(gid+8, 2tg) c3=(gid+8, 2tg+1)
    const int og0 = oty * 128 + warp_m * 64;
#pragma unroll
    for (int mt = 0; mt < 4; ++mt) {
        int o0 = og0 + mt * 16 + gid;
        float s0 = g_sigma[b * On + o0];
        float s1 = g_sigma[b * On + o0 + 8];
        float* r0 = out + (size_t)(b * On + o0) * 1024;
        float* r1 = out + (size_t)(b * On + o0 + 8) * 1024;
#pragma unroll
        for (int nt = 0; nt < 4; ++nt) {
            int n = warp_n * 32 + nt * 8 + 2 * tg;
            int off = (y0 + (n >> 5)) * 32 + (n & 31);
            float2 v0 = make_float2(acc[mt][nt][0] * s0, acc[mt][nt][1] * s0);
            float2 v1 = make_float2(acc[mt][nt][2] * s1, acc[mt][nt][3] * s1);
            *(float2*)(r0 + off) = v0;
            *(float2*)(r1 + off) = v1;
        }
    }
}

// ---------------------------------------------------------------------------
extern "C" void kernel_launch(void* const* d_in, const int* in_sizes, int n_in,
                              void* d_out, int out_size) {
    const float* x     = (const float*)d_in[0];  // [16,512,32,32]
    const float* style = (const float*)d_in[1];  // [16,512]
    const float* wt    = (const float*)d_in[2];  // [512,512,3,3]
    float* out = (float*)d_out;

    const int smem_bytes = 2 * 32 * XS * 4;      // 63488
    cudaFuncSetAttribute(conv_mma_kernel,
                         cudaFuncAttributeMaxDynamicSharedMemorySize, smem_bytes);

    wsq_kernel<<<(On * Cn + 255) / 256, 256>>>(wt);
    wfrag_kernel<<<(9 * 32 * 64 * 32 + 255) / 256, 256>>>(wt);
    sigma_kernel<<<dim3(On, Bn), 256>>>(style);
    conv_mma_kernel<<<dim3(8, 4, Bn), 256, smem_bytes>>>(x, style, out);
}

// round 17
// speedup vs baseline: 1.4240x; 1.4240x over previous
#include <cuda_runtime.h>
#include <cstdint>

// ModulatedConv2D: B=16, Cin=Cout=512, H=W=32, k=3, pad=1.
// out[b,o] = sigma[b,o] * conv2d( x[b,i]*style[b,i], weight*GAIN )[o]
// Implicit GEMM via mma.sync m16n8k8 tf32.
// R16: all-smem operand path. Per 16-ch chunk: A (9 taps, 72KB) cp.async-staged
// single-buffered; halo cp.async double-buffered raw; style*x + tf32 round
// folded into B-fragment register path.

#define Bn 16
#define Cn 512
#define On 512
#define GAINF 0.014731391274719738f  // 1/sqrt(512*9)

__device__ float g_wsq[On * Cn];
__device__ float g_sigma[Bn * On];
// A fragments: [tap(9)][otile16(32)][kstep8(64)][lane(32)][4 regs], tf32 bits
__device__ uint32_t g_wA[9 * 32 * 64 * 32 * 4];

// ---------------------------------------------------------------------------
__global__ void wsq_kernel(const float* __restrict__ wt) {
    int idx = blockIdx.x * 256 + threadIdx.x;
    if (idx < On * Cn) {
        const float* p = wt + idx * 9;
        float s = 0.f;
#pragma unroll
        for (int k = 0; k < 9; ++k) { float v = p[k]; s += v * v; }
        g_wsq[idx] = s;
    }
}

// m16n8k8 A layout: a0=(gid,tg) a1=(gid+8,tg) a2=(gid,tg+4) a3=(gid+8,tg+4)
__global__ void wfrag_kernel(const float* __restrict__ wt) {
    int id = blockIdx.x * 256 + threadIdx.x;
    if (id >= 9 * 32 * 64 * 32) return;
    int lane = id & 31;
    int ksg  = (id >> 5) & 63;
    int otg  = (id >> 11) & 31;
    int tap  = id >> 16;
    int gid = lane >> 2, tg = lane & 3;
    int o = otg * 16 + gid;
    int k = ksg * 8 + tg;
    float f0 = wt[((o    ) * Cn + k    ) * 9 + tap] * GAINF;
    float f1 = wt[((o + 8) * Cn + k    ) * 9 + tap] * GAINF;
    float f2 = wt[((o    ) * Cn + k + 4) * 9 + tap] * GAINF;
    float f3 = wt[((o + 8) * Cn + k + 4) * 9 + tap] * GAINF;
    uint32_t u0, u1, u2, u3;
    asm("cvt.rna.tf32.f32 %0, %1;" : "=r"(u0) : "f"(f0));
    asm("cvt.rna.tf32.f32 %0, %1;" : "=r"(u1) : "f"(f1));
    asm("cvt.rna.tf32.f32 %0, %1;" : "=r"(u2) : "f"(f2));
    asm("cvt.rna.tf32.f32 %0, %1;" : "=r"(u3) : "f"(f3));
    ((uint4*)g_wA)[id] = make_uint4(u0, u1, u2, u3);
}

// ---------------------------------------------------------------------------
__global__ void sigma_kernel(const float* __restrict__ style) {
    int o = blockIdx.x, b = blockIdx.y, t = threadIdx.x;
    float s = 0.f;
    for (int i = t; i < Cn; i += 256) {
        float st = style[b * Cn + i];
        s += st * st * g_wsq[o * Cn + i];
    }
    __shared__ float red[8];
#pragma unroll
    for (int off = 16; off; off >>= 1) s += __shfl_xor_sync(0xffffffffu, s, off);
    if ((t & 31) == 0) red[t >> 5] = s;
    __syncthreads();
    if (t < 8) {
        s = red[t];
#pragma unroll
        for (int off = 4; off; off >>= 1) s += __shfl_xor_sync(0xffu, s, off);
        if (t == 0) g_sigma[b * On + o] = rsqrtf(GAINF * GAINF * s + 1e-8f);
    }
}

// ---------------------------------------------------------------------------
// Halo: per channel XS=248 floats (mod 32 = 24 -> conflict-free tg*XS strides),
// row stride 40, x-col c at idx c+4 (16B-aligned interior for cp.async.cg).
// ---------------------------------------------------------------------------
#define XS 248
#define RS 40
#define HALO_F   (16 * XS)                 // floats per halo buffer (16 ch)
#define SA_OFF   (2 * HALO_F * 4)          // A region byte offset  = 31744
#define SA_BYTES (9 * 8 * 2 * 32 * 16)     // 73728
#define SST_OFF  (SA_OFF + SA_BYTES)       // style region          = 105472
#define SMEM_B   (SST_OFF + 64)            // 105536

#define MMA_TF32(c, a, bb0, bb1)                                              \
    asm("mma.sync.aligned.m16n8k8.row.col.f32.tf32.tf32.f32 "                 \
        "{%0,%1,%2,%3}, {%4,%5,%6,%7}, {%8,%9}, {%0,%1,%2,%3};"               \
        : "+f"((c)[0]), "+f"((c)[1]), "+f"((c)[2]), "+f"((c)[3])              \
        : "r"((a).x), "r"((a).y), "r"((a).z), "r"((a).w), "r"(bb0), "r"(bb1))

__device__ __forceinline__ uint32_t smem_u32(const void* p) {
    uint32_t a;
    asm("{ .reg .u64 t; cvta.to.shared.u64 t, %1; cvt.u32.u64 %0, t; }" : "=r"(a) : "l"(p));
    return a;
}
__device__ __forceinline__ void cp16(uint32_t dst, const void* src) {
    asm volatile("cp.async.cg.shared.global [%0], [%1], 16;" :: "r"(dst), "l"(src));
}
__device__ __forceinline__ void cp_commit() {
    asm volatile("cp.async.commit_group;" ::: "memory");
}
__device__ __forceinline__ void cp_wait0() {
    asm volatile("cp.async.wait_group 0;" ::: "memory");
}

// stage one 16-channel halo chunk (raw x, 16 ch x 6 rows x 8 x 16B)
__device__ __forceinline__ void issue_halo(const float* __restrict__ x,
                                           uint32_t sbuf_u32, int bC, int ic0,
                                           int y0, int tid) {
#pragma unroll
    for (int j = 0; j < 3; ++j) {
        int idx = j * 256 + tid;            // 0..767
        int ch  = idx / 48;
        int rem = idx - ch * 48;
        int r   = rem >> 3;
        int c16 = rem & 7;
        int gy  = y0 + r - 1;
        if ((unsigned)gy < 32u) {
            const float* src = x + ((size_t)(bC + ic0 + ch) * 32 + gy) * 32 + c16 * 4;
            uint32_t dst = sbuf_u32 + (uint32_t)(ch * XS + r * RS + 4 + c16 * 4) * 4u;
            cp16(dst, src);
        }
    }
}

__global__ void __launch_bounds__(256, 2)
conv_mma_kernel(const float* __restrict__ x, const float* __restrict__ style,
                float* __restrict__ out) {
    extern __shared__ __align__(16) float sXH[];   // [2 halo bufs][A][style]

    const int b   = blockIdx.z;
    const int oty = blockIdx.y;          // o-tile: 128 channels
    const int y0  = blockIdx.x * 4;      // 4 output rows
    const int tid = threadIdx.x;
    const int wid = tid >> 5, lane = tid & 31;
    const int warp_m = wid >> 2;         // 0..1 : 64 o-channels
    const int warp_n = wid & 3;          // 0..3 : output row within tile
    const int gid = lane >> 2, tg = lane & 3;
    const int bC = b * Cn;
    const uint32_t sb = smem_u32(sXH);
    const uint4*  sA  = (const uint4*)((char*)sXH + SA_OFF);
    const float*  sSt = (const float*)((char*)sXH + SST_OFF);

    // ---- zero halo buffers once (borders/invalid rows stay zero) ----
#pragma unroll
    for (int j = 0; j < 8; ++j) {
        int e = j * 256 + tid;             // 2*HALO_F/4 = 1984 float4
        if (e < 2 * HALO_F / 4)
            ((float4*)sXH)[e] = make_float4(0.f, 0.f, 0.f, 0.f);
    }
    __syncthreads();

    issue_halo(x, sb, bC, 0, y0, tid);
    cp_commit();                            // group: halo(0)

    float acc[4][4][4];
#pragma unroll
    for (int mt = 0; mt < 4; ++mt)
#pragma unroll
        for (int nt = 0; nt < 4; ++nt)
#pragma unroll
            for (int c = 0; c < 4; ++c) acc[mt][nt][c] = 0.f;

#pragma unroll 1
    for (int ci = 0; ci < 32; ++ci) {
        const int ic0 = ci * 16;

        // ---- stage A slice (9 taps x 8 otg x 2 ks x 32 lanes x 16B) + style ----
#pragma unroll
        for (int j = 0; j < 18; ++j) {
            int idx  = j * 256 + tid;       // 0..4607
            int ln   = idx & 31;
            int ksl  = (idx >> 5) & 1;
            int otg  = (idx >> 6) & 7;
            int tap  = idx >> 9;
            const char* src = (const char*)g_wA +
                ((size_t)((tap * 32 + oty * 8 + otg) * 64 + ci * 2 + ksl) * 32 + ln) * 16;
            uint32_t dst = sb + SA_OFF +
                (uint32_t)(((tap * 8 + otg) * 2 + ksl) * 32 + ln) * 16u;
            cp16(dst, src);
        }
        if (tid < 4)
            cp16(sb + SST_OFF + tid * 16u, style + bC + ic0 + tid * 4);
        cp_commit();                        // group: A(ci)+style(ci)

        cp_wait0();                         // halo(ci) + A(ci) landed
        __syncthreads();

        if (ci < 31) {
            issue_halo(x, sb + (uint32_t)((~ci & 1) * HALO_F) * 4u,
                       bC, ic0 + 16, y0, tid);
            cp_commit();                    // group: halo(ci+1), overlaps taps
        }

        const float* cur = sXH + (ci & 1) * HALO_F;

        // ---- 9 taps x 2 k-steps, all operands from smem ----
#pragma unroll 1
        for (int tap = 0; tap < 9; ++tap) {
            const int dy = tap / 3, dx = tap - dy * 3;
            const float* pBt = cur + (warp_n + dy) * RS + dx + 3 + tg * XS;
            const uint4* pAt = sA + (tap * 8 + warp_m * 4) * 64 + lane;
#pragma unroll
            for (int ks = 0; ks < 2; ++ks) {
                uint4 A[4];
#pragma unroll
                for (int mt = 0; mt < 4; ++mt)
                    A[mt] = pAt[ks * 32 + mt * 64];          // LDS.128
                const float* pB = pBt + ks * (8 * XS);
                float s0 = sSt[ks * 8 + tg];
                float s1 = sSt[ks * 8 + tg + 4];
                uint32_t b0[4], b1[4];
#pragma unroll
                for (int nt = 0; nt < 4; ++nt) {
                    float v0 = pB[nt * 8 + gid] * s0;
                    float v1 = pB[nt * 8 + gid + 4 * XS] * s1;
                    asm("cvt.rna.tf32.f32 %0, %1;" : "=r"(b0[nt]) : "f"(v0));
                    asm("cvt.rna.tf32.f32 %0, %1;" : "=r"(b1[nt]) : "f"(v1));
                }
#pragma unroll
                for (int mt = 0; mt < 4; ++mt)
#pragma unroll
                    for (int nt = 0; nt < 4; ++nt)
                        MMA_TF32(acc[mt][nt], A[mt], b0[nt], b1[nt]);
            }
        }
        __syncthreads();   // all reads of A/style done before next overwrite
    }

    // ---- epilogue: demodulate, direct float2 stores ----
    // C layout: c0=(gid, 2tg) c1=(gid, 2tg+1) c2=(gid+8, 2tg) c3=(gid+8, 2tg+1)
    const int og0 = oty * 128 + warp_m * 64;
#pragma unroll
    for (int mt = 0; mt < 4; ++mt) {
        int o0 = og0 + mt * 16 + gid;
        float s0 = g_sigma[b * On + o0];
        float s1 = g_sigma[b * On + o0 + 8];
        float* r0 = out + (size_t)(b * On + o0) * 1024;
        float* r1 = out + (size_t)(b * On + o0 + 8) * 1024;
#pragma unroll
        for (int nt = 0; nt < 4; ++nt) {
            int n = warp_n * 32 + nt * 8 + 2 * tg;
            int off = (y0 + (n >> 5)) * 32 + (n & 31);
            float2 v0 = make_float2(acc[mt][nt][0] * s0, acc[mt][nt][1] * s0);
            float2 v1 = make_float2(acc[mt][nt][2] * s1, acc[mt][nt][3] * s1);
            *(float2*)(r0 + off) = v0;
            *(float2*)(r1 + off) = v1;
        }
    }
}

// ---------------------------------------------------------------------------
extern "C" void kernel_launch(void* const* d_in, const int* in_sizes, int n_in,
                              void* d_out, int out_size) {
    const float* x     = (const float*)d_in[0];  // [16,512,32,32]
    const float* style = (const float*)d_in[1];  // [16,512]
    const float* wt    = (const float*)d_in[2];  // [512,512,3,3]
    float* out = (float*)d_out;

    cudaFuncSetAttribute(conv_mma_kernel,
                         cudaFuncAttributeMaxDynamicSharedMemorySize, SMEM_B);

    wsq_kernel<<<(On * Cn + 255) / 256, 256>>>(wt);
    wfrag_kernel<<<(9 * 32 * 64 * 32 + 255) / 256, 256>>>(wt);
    sigma_kernel<<<dim3(On, Bn), 256>>>(style);
    conv_mma_kernel<<<dim3(8, 4, Bn), 256, SMEM_B>>>(x, style, out);
}